// round 11
// baseline (speedup 1.0000x reference)
#include <cuda_runtime.h>
#include <cuda_bf16.h>
#include <cstdint>

#define B_    16
#define S_    10
#define D_    128
#define C_    256
#define NTOK  65536
#define NPB   4096
#define T_    20
#define CHUNK 128
#define NCHUNK 32
#define QSCALE 0.08838834764831845f

// ---- scratch ----
__device__ __nv_bfloat16 g_k[NTOK * D_];          // [tok][d]
__device__ __nv_bfloat16 g_v[NTOK * D_];          // [tok][d]
__device__ __nv_bfloat16 g_wkT[D_ * C_];          // Wk^T [d][c]
__device__ __nv_bfloat16 g_wvT[D_ * C_];          // Wv^T [d][c]
__device__ __nv_bfloat16 g_qb[B_ * 16 * D_];      // [b][16 slots(pad)][d]
__device__ float g_slots[B_ * S_ * D_];
__device__ float g_pnum[(size_t)B_ * NCHUNK * S_ * D_];
__device__ float g_pden[B_ * NCHUNK * S_];

__device__ __forceinline__ float2 warpRed2(float a, float b) {
    #pragma unroll
    for (int o = 16; o > 0; o >>= 1) {
        a += __shfl_xor_sync(0xffffffffu, a, o);
        b += __shfl_xor_sync(0xffffffffu, b, o);
    }
    return make_float2(a, b);
}
__device__ __forceinline__ float warpRed1(float a) {
    #pragma unroll
    for (int o = 16; o > 0; o >>= 1) a += __shfl_xor_sync(0xffffffffu, a, o);
    return a;
}

__device__ __forceinline__ uint32_t s2u(const void* p) {
    return (uint32_t)__cvta_generic_to_shared(p);
}
__device__ __forceinline__ float bf(const __nv_bfloat16 x) { return __bfloat162float(x); }

#define LDSM4(r, addr)                                                          \
    asm volatile("ldmatrix.sync.aligned.m8n8.x4.shared.b16 {%0,%1,%2,%3}, [%4];"\
                 : "=r"((r)[0]), "=r"((r)[1]), "=r"((r)[2]), "=r"((r)[3])       \
                 : "r"(addr))

#define LDSM4T(r, addr)                                                         \
    asm volatile("ldmatrix.sync.aligned.m8n8.x4.trans.shared.b16 {%0,%1,%2,%3}, [%4];"\
                 : "=r"((r)[0]), "=r"((r)[1]), "=r"((r)[2]), "=r"((r)[3])       \
                 : "r"(addr))

#define MMA_BF16(d, a, b0, b1)                                                  \
    asm volatile("mma.sync.aligned.m16n8k16.row.col.f32.bf16.bf16.f32 "         \
                 "{%0,%1,%2,%3}, {%4,%5,%6,%7}, {%8,%9}, {%0,%1,%2,%3};"        \
                 : "+f"((d)[0]), "+f"((d)[1]), "+f"((d)[2]), "+f"((d)[3])       \
                 : "r"((a)[0]), "r"((a)[1]), "r"((a)[2]), "r"((a)[3]),          \
                   "r"(b0), "r"(b1))

// cp.async 16B (L2-only .cg path) + group control
#define CPASYNC16(dst, src)                                                     \
    asm volatile("cp.async.cg.shared.global [%0], [%1], 16;"                    \
                 :: "r"(dst), "l"(src) : "memory")
#define CPCOMMIT() asm volatile("cp.async.commit_group;" ::: "memory")
#define CPWAIT(n)  asm volatile("cp.async.wait_group %0;" :: "n"(n) : "memory")

// ============================================================================
// Kernel 0: K/V weight transpose + bf16 convert
// ============================================================================
__global__ void k_prep(const float* __restrict__ Wk, const float* __restrict__ Wv)
{
    int d = blockIdx.x;
    int c = threadIdx.x;
    g_wkT[d * C_ + c] = __float2bfloat16(Wk[c * D_ + d]);
    g_wvT[d * C_ + c] = __float2bfloat16(Wv[c * D_ + d]);
}

// ============================================================================
// Kernel 1: fused LayerNorm + K,V projection (bf16 mma.sync).
// 512 tokens/block, 512 threads, 128 blocks (single wave). obs via __ldcs.
// ============================================================================
#define XSTRIDE 264
#define SMEM1 (3 * 128 * XSTRIDE * 2)
__global__ __launch_bounds__(512, 1) void k_ln_kv(
    const float* __restrict__ obs, const float* __restrict__ niw,
    const float* __restrict__ nib)
{
    extern __shared__ char smx[];
    __nv_bfloat16* xs  = (__nv_bfloat16*)smx;           // [128][264]
    __nv_bfloat16* wks = xs + 128 * XSTRIDE;
    __nv_bfloat16* wvs = wks + 128 * XSTRIDE;

    const int tid  = threadIdx.x;
    const int wid  = tid >> 5;
    const int lane = tid & 31;
    const int tblk = blockIdx.x * 512;

    // stage bf16 transposed weights once per block
    {
        const uint4* gk4 = (const uint4*)g_wkT;
        const uint4* gv4 = (const uint4*)g_wvT;
        #pragma unroll
        for (int i = 0; i < 8; i++) {
            int u = tid + i * 512;
            int row = u >> 5, c = u & 31;
            *(uint4*)((char*)wks + row * (XSTRIDE * 2) + c * 16) = gk4[u];
            *(uint4*)((char*)wvs + row * (XSTRIDE * 2) + c * 16) = gv4[u];
        }
    }

    const int c0 = lane * 4;
    float4 nw0 = *(const float4*)(niw + c0);
    float4 nw1 = *(const float4*)(niw + c0 + 128);
    float4 nb0 = *(const float4*)(nib + c0);
    float4 nb1 = *(const float4*)(nib + c0 + 128);

    const int mat = wid >> 3;          // 0 = K, 1 = V
    const int wm  = wid & 3;
    const int wn  = (wid >> 2) & 1;
    const __nv_bfloat16* wsm = mat ? wvs : wks;
    const int ga = lane >> 3, ra = lane & 7;
    const uint32_t aA0 = s2u(xs) +
        (uint32_t)(((wm * 32 + ra + ((ga & 1) << 3)) * XSTRIDE + ((ga >> 1) << 3)) * 2);
    const uint32_t aB0 = s2u(wsm) +
        (uint32_t)(((wn * 64 + ra + ((ga >> 1) << 3)) * XSTRIDE + ((ga & 1) << 3)) * 2);
    const int qrow = lane >> 2;
    const int qcol = (lane & 3) * 2;
    __nv_bfloat16* gout = mat ? g_v : g_k;

    #pragma unroll 1
    for (int tile = 0; tile < 4; tile++) {
        const int t0 = tblk + tile * 128;
        __syncthreads();
        // ---- LayerNorm: warp owns 8 rows (streaming loads) ----
        #pragma unroll
        for (int i = 0; i < 8; i++) {
            int r = wid * 8 + i;
            const float4* src = (const float4*)(obs + (size_t)(t0 + r) * C_);
            float4 v0 = __ldcs(src + lane);
            float4 v1 = __ldcs(src + lane + 32);
            float s  = v0.x + v0.y + v0.z + v0.w + v1.x + v1.y + v1.z + v1.w;
            float ss = v0.x*v0.x + v0.y*v0.y + v0.z*v0.z + v0.w*v0.w
                     + v1.x*v1.x + v1.y*v1.y + v1.z*v1.z + v1.w*v1.w;
            float2 red = warpRed2(s, ss);
            float mu  = red.x * (1.0f / 256.0f);
            float var = red.y * (1.0f / 256.0f) - mu * mu;
            float rsg = rsqrtf(var + 1e-5f);
            char* xr = (char*)xs + r * (XSTRIDE * 2);
            *(__nv_bfloat162*)(xr + (c0 + 0) * 2) =
                __floats2bfloat162_rn((v0.x - mu) * rsg * nw0.x + nb0.x,
                                      (v0.y - mu) * rsg * nw0.y + nb0.y);
            *(__nv_bfloat162*)(xr + (c0 + 2) * 2) =
                __floats2bfloat162_rn((v0.z - mu) * rsg * nw0.z + nb0.z,
                                      (v0.w - mu) * rsg * nw0.w + nb0.w);
            *(__nv_bfloat162*)(xr + (c0 + 128) * 2) =
                __floats2bfloat162_rn((v1.x - mu) * rsg * nw1.x + nb1.x,
                                      (v1.y - mu) * rsg * nw1.y + nb1.y);
            *(__nv_bfloat162*)(xr + (c0 + 130) * 2) =
                __floats2bfloat162_rn((v1.z - mu) * rsg * nw1.z + nb1.z,
                                      (v1.w - mu) * rsg * nw1.w + nb1.w);
        }
        __syncthreads();

        // ---- MMA: warp computes 32(m) x 64(n) for its matrix ----
        float acc[2][8][4];
        #pragma unroll
        for (int mi = 0; mi < 2; mi++)
            #pragma unroll
            for (int nj = 0; nj < 8; nj++)
                #pragma unroll
                for (int e = 0; e < 4; e++) acc[mi][nj][e] = 0.f;

        uint32_t aA = aA0, aB = aB0;
        #pragma unroll 1
        for (int s = 0; s < 16; s++) {
            uint32_t A0[4], A1[4], Bx[4][4];
            LDSM4(A0, aA);
            LDSM4(A1, aA + 16 * (XSTRIDE * 2));
            #pragma unroll
            for (int j = 0; j < 4; j++)
                LDSM4(Bx[j], aB + j * 16 * (XSTRIDE * 2));
            #pragma unroll
            for (int nj = 0; nj < 8; nj++) {
                uint32_t b0 = Bx[nj >> 1][(nj & 1) * 2];
                uint32_t b1 = Bx[nj >> 1][(nj & 1) * 2 + 1];
                MMA_BF16(acc[0][nj], A0, b0, b1);
                MMA_BF16(acc[1][nj], A1, b0, b1);
            }
            aA += 32;
            aB += 32;
        }

        // ---- epilogue: [t][d] for both K and V ----
        #pragma unroll
        for (int mi = 0; mi < 2; mi++) {
            #pragma unroll
            for (int nj = 0; nj < 8; nj++) {
                int c  = wn * 64 + nj * 8 + qcol;
                int r0 = t0 + wm * 32 + mi * 16 + qrow;
                *(__nv_bfloat162*)(gout + (size_t)r0 * D_ + c) =
                    __floats2bfloat162_rn(acc[mi][nj][0], acc[mi][nj][1]);
                *(__nv_bfloat162*)(gout + (size_t)(r0 + 8) * D_ + c) =
                    __floats2bfloat162_rn(acc[mi][nj][2], acc[mi][nj][3]);
            }
        }
    }
}

// ============================================================================
// LN stats helper (256-thread block, 128 live values)
// ============================================================================
__device__ __forceinline__ void ln_stats(float x, float* r1, float* r2,
                                         float& mu, float& rs) {
    float2 red = warpRed2(x, x * x);
    int wid = threadIdx.x >> 5, lane = threadIdx.x & 31;
    if (lane == 0) { r1[wid] = red.x; r2[wid] = red.y; }
    __syncthreads();
    float Sm = 0.f, Sq = 0.f;
    #pragma unroll
    for (int i = 0; i < 8; i++) { Sm += r1[i]; Sq += r2[i]; }
    mu = Sm * (1.0f / 128.0f);
    float var = Sq * (1.0f / 128.0f) - mu * mu;
    rs = rsqrtf(var + 1e-5f);
}

// ============================================================================
// Kernel 2: slot init + q-pad zero + LN + q projection (fused).
// ============================================================================
__global__ void k_sq_init(const float* __restrict__ noise, const float* __restrict__ smu,
                          const float* __restrict__ sls, const float* __restrict__ nsw,
                          const float* __restrict__ nsb, const float* __restrict__ Wq)
{
    __shared__ float sl[128];
    __shared__ float hm[128];
    __shared__ float hid[256];
    __shared__ float r1[8], r2[8];
    const int tid = threadIdx.x;
    const int b = blockIdx.x / 10;
    const int s = blockIdx.x % 10;

    if (tid < 128) {
        float v = smu[tid] + expf(sls[tid]) * noise[blockIdx.x * 128 + tid];
        g_slots[blockIdx.x * 128 + tid] = v;
        sl[tid] = v;
        if (s < 6)   // zero g_qb pad rows 10..15
            g_qb[b * 2048 + (10 + s) * 128 + tid] = __float2bfloat16(0.f);
    }
    __syncthreads();

    float x = (tid < 128) ? sl[tid] : 0.f;
    float mu, rs;
    ln_stats(x, r1, r2, mu, rs);
    if (tid < 128) hm[tid] = (x - mu) * rs * nsw[tid] + nsb[tid];
    __syncthreads();
    {
        int d = tid & 127, half = tid >> 7;
        const float* wq = Wq + half * 64 * 128;
        const float* hh = hm + half * 64;
        float a0 = 0, a1 = 0, a2 = 0, a3 = 0;
        #pragma unroll
        for (int c = 0; c < 64; c += 4) {
            a0 += hh[c + 0] * wq[(c + 0) * 128 + d];
            a1 += hh[c + 1] * wq[(c + 1) * 128 + d];
            a2 += hh[c + 2] * wq[(c + 2) * 128 + d];
            a3 += hh[c + 3] * wq[(c + 3) * 128 + d];
        }
        hid[tid] = (a0 + a1) + (a2 + a3);
    }
    __syncthreads();
    if (tid < 128)
        g_qb[b * 2048 + s * 128 + tid] =
            __float2bfloat16((hid[tid] + hid[tid + 128]) * QSCALE);
}

// ============================================================================
// Kernel 3: fused attention chunk, cp.async K/V prefetch breaking phase
// lockstep. grid (NCHUNK, B_), 256 threads, 2 CTAs/SM (87KB smem).
// ============================================================================
#define TS 136
#define LSTR 132
#define ATT_SMEM (2*128*TS*2 + 16*TS*2 + 16*TS*2 + 16*LSTR*4)
__global__ __launch_bounds__(256, 2) void k_attn()
{
    extern __shared__ char sm2[];
    __nv_bfloat16* tileK = (__nv_bfloat16*)sm2;             // [128][136]
    __nv_bfloat16* tileV = tileK + 128 * TS;                // [128][136]
    __nv_bfloat16* Qs    = tileV + 128 * TS;                // [16][136]
    __nv_bfloat16* aBm   = Qs + 16 * TS;                    // attn bf16 [16][136]
    float* Ls            = (float*)(aBm + 16 * TS);         // logits [16][132]

    const int tid  = threadIdx.x;
    const int w    = tid >> 5;
    const int lane = tid & 31;
    const int ck   = blockIdx.x;
    const int b    = blockIdx.y;

    // ---- issue async loads: K (group A) then V (group B) ----
    {
        const uint4* srcK = (const uint4*)(g_k + ((size_t)b * NPB + ck * CHUNK) * D_);
        const uint4* srcV = (const uint4*)(g_v + ((size_t)b * NPB + ck * CHUNK) * D_);
        const uint32_t dK = s2u(tileK), dV = s2u(tileV);
        #pragma unroll
        for (int i = 0; i < 8; i++) {
            int u = tid + i * 256;
            int row = u >> 4, c = u & 15;
            CPASYNC16(dK + row * (TS * 2) + c * 16, srcK + u);
        }
        CPCOMMIT();
        #pragma unroll
        for (int i = 0; i < 8; i++) {
            int u = tid + i * 256;
            int row = u >> 4, c = u & 15;
            CPASYNC16(dV + row * (TS * 2) + c * 16, srcV + u);
        }
        CPCOMMIT();
    }

    // load Q [16][128] : 256 uint4 (small, regular)
    {
        int row = tid >> 4, c = tid & 15;
        *(uint4*)((char*)Qs + row * (TS * 2) + c * 16) =
            ((const uint4*)(g_qb + b * 2048))[tid];
    }
    if (tid < 102) {
        *(uint4*)((char*)aBm + 10 * (TS * 2) + tid * 16) = make_uint4(0, 0, 0, 0);
    }

    CPWAIT(1);          // K tile ready (V may still be in flight)
    __syncthreads();

    const int ga = lane >> 3, ra = lane & 7;
    const int qrow = lane >> 2, qcol = (lane & 3) * 2;
    const uint32_t baseA_q = s2u(Qs) +
        (uint32_t)(((ra + ((ga & 1) << 3)) * TS + ((ga >> 1) << 3)) * 2);
    const uint32_t baseB_k = s2u(tileK) +
        (uint32_t)(((w * 16 + ra + ((ga >> 1) << 3)) * TS + ((ga & 1) << 3)) * 2);

    // ---- logits MMA: l[s][t] ----
    {
        float lacc[2][4] = {{0,0,0,0},{0,0,0,0}};
        #pragma unroll
        for (int ks = 0; ks < 8; ks++) {
            uint32_t A[4], Bx[4];
            LDSM4(A, baseA_q + ks * 32);
            LDSM4(Bx, baseB_k + ks * 32);
            MMA_BF16(lacc[0], A, Bx[0], Bx[1]);
            MMA_BF16(lacc[1], A, Bx[2], Bx[3]);
        }
        #pragma unroll
        for (int nj = 0; nj < 2; nj++) {
            int t = w * 16 + nj * 8 + qcol;
            Ls[qrow * LSTR + t]           = lacc[nj][0];
            Ls[qrow * LSTR + t + 1]       = lacc[nj][1];
            Ls[(qrow + 8) * LSTR + t]     = lacc[nj][2];
            Ls[(qrow + 8) * LSTR + t + 1] = lacc[nj][3];
        }
    }
    __syncthreads();

    // ---- softmax over 10 slots per token ----
    if (tid < 128) {
        float v[10]; float m = -1e30f;
        #pragma unroll
        for (int s = 0; s < 10; s++) { v[s] = Ls[s * LSTR + tid]; m = fmaxf(m, v[s]); }
        float sum = 0.f;
        #pragma unroll
        for (int s = 0; s < 10; s++) { v[s] = __expf(v[s] - m); sum += v[s]; }
        float inv = 1.0f / sum;
        #pragma unroll
        for (int s = 0; s < 10; s++) aBm[s * TS + tid] = __float2bfloat16(v[s] * inv);
    }
    __syncthreads();

    // ---- denominators ----
    for (int s = w; s < 10; s += 8) {
        float p = bf(aBm[s * TS + lane]) + bf(aBm[s * TS + lane + 32])
                + bf(aBm[s * TS + lane + 64]) + bf(aBm[s * TS + lane + 96]);
        p = warpRed1(p);
        if (lane == 0) g_pden[(b * NCHUNK + ck) * S_ + s] = p;
    }

    CPWAIT(0);          // V tile ready
    __syncthreads();

    // ---- numerator MMA: upd[s][d] = sum_t attn[s][t] * V[t][d] (trans B) ----
    {
        const uint32_t baseA_a = s2u(aBm) +
            (uint32_t)(((ra + ((ga & 1) << 3)) * TS + ((ga >> 1) << 3)) * 2);
        const uint32_t baseB_v = s2u(tileV) +
            (uint32_t)(((((ga & 1) << 3) + ra) * TS + w * 16 + ((ga >> 1) << 3)) * 2);
        float nacc[2][4] = {{0,0,0,0},{0,0,0,0}};
        #pragma unroll
        for (int ks = 0; ks < 8; ks++) {
            uint32_t A[4], Bt[4];
            LDSM4(A, baseA_a + ks * 32);
            LDSM4T(Bt, baseB_v + ks * (16 * TS * 2));
            MMA_BF16(nacc[0], A, Bt[0], Bt[1]);
            MMA_BF16(nacc[1], A, Bt[2], Bt[3]);
        }
        float* dst = g_pnum + (size_t)(b * NCHUNK + ck) * S_ * D_;
        #pragma unroll
        for (int nj = 0; nj < 2; nj++) {
            int d = w * 16 + nj * 8 + qcol;
            *(float2*)(dst + qrow * D_ + d) = make_float2(nacc[nj][0], nacc[nj][1]);
            if (qrow + 8 < 10)
                *(float2*)(dst + (qrow + 8) * D_ + d) = make_float2(nacc[nj][2], nacc[nj][3]);
        }
    }
}

// ============================================================================
// Kernel 4: slot update + q projection.  grid 160, 256 thr.
// ============================================================================
__global__ void k_slotq(const float* __restrict__ nmw, const float* __restrict__ nmb,
                        const float* __restrict__ w1, const float* __restrict__ b1,
                        const float* __restrict__ w2, const float* __restrict__ b2,
                        const float* __restrict__ nsw, const float* __restrict__ nsb,
                        const float* __restrict__ Wq)
{
    __shared__ float sl[128];
    __shared__ float hm[128];
    __shared__ float hid[256];
    __shared__ float r1[8], r2[8];
    __shared__ float sden;
    const int tid = threadIdx.x;
    const int b = blockIdx.x / 10;
    const int s = blockIdx.x % 10;

    if ((tid >> 5) == 4) {
        int lane = tid & 31;
        float p = g_pden[(b * NCHUNK + lane) * S_ + s];
        p = warpRed1(p);
        if (lane == 0) sden = p;
    }
    float u0 = 0, u1 = 0, u2 = 0, u3 = 0;
    if (tid < 128) {
        const float* src = g_pnum + ((size_t)(b * NCHUNK) * S_ + s) * D_ + tid;
        #pragma unroll
        for (int ch = 0; ch < NCHUNK; ch += 4) {
            u0 += __ldcs(src + (size_t)(ch + 0) * S_ * D_);
            u1 += __ldcs(src + (size_t)(ch + 1) * S_ * D_);
            u2 += __ldcs(src + (size_t)(ch + 2) * S_ * D_);
            u3 += __ldcs(src + (size_t)(ch + 3) * S_ * D_);
        }
    }
    __syncthreads();
    float slot_new = 0.f;
    if (tid < 128)
        slot_new = g_slots[(b * S_ + s) * D_ + tid]
                 + ((u0 + u1) + (u2 + u3)) / (sden + 1e-8f);
    float mu, rs;
    ln_stats(tid < 128 ? slot_new : 0.f, r1, r2, mu, rs);
    if (tid < 128) hm[tid] = (slot_new - mu) * rs * nmw[tid] + nmb[tid];
    __syncthreads();
    {
        float a0 = 0, a1 = 0, a2 = 0, a3 = 0;
        #pragma unroll
        for (int c = 0; c < 128; c += 4) {
            a0 += hm[c + 0] * w1[(c + 0) * 256 + tid];
            a1 += hm[c + 1] * w1[(c + 1) * 256 + tid];
            a2 += hm[c + 2] * w1[(c + 2) * 256 + tid];
            a3 += hm[c + 3] * w1[(c + 3) * 256 + tid];
        }
        hid[tid] = fmaxf(b1[tid] + (a0 + a1) + (a2 + a3), 0.f);
    }
    __syncthreads();
    if (tid < 128) {
        float o0 = 0, o1 = 0, o2 = 0, o3 = 0;
        #pragma unroll 16
        for (int j = 0; j < 256; j += 4) {
            o0 += hid[j + 0] * w2[(j + 0) * 128 + tid];
            o1 += hid[j + 1] * w2[(j + 1) * 128 + tid];
            o2 += hid[j + 2] * w2[(j + 2) * 128 + tid];
            o3 += hid[j + 3] * w2[(j + 3) * 128 + tid];
        }
        float sf = slot_new + b2[tid] + (o0 + o1) + (o2 + o3);
        sl[tid] = sf;
        g_slots[(b * S_ + s) * D_ + tid] = sf;
    }
    __syncthreads();

    // LN(ns) + q = h @ Wq * scale (split-k over 2 halves)
    float x = (tid < 128) ? sl[tid] : 0.f;
    ln_stats(x, r1, r2, mu, rs);
    if (tid < 128) hm[tid] = (x - mu) * rs * nsw[tid] + nsb[tid];
    __syncthreads();
    {
        int d = tid & 127, half = tid >> 7;
        const float* wq = Wq + half * 64 * 128;
        const float* hh = hm + half * 64;
        float a0 = 0, a1 = 0, a2 = 0, a3 = 0;
        #pragma unroll
        for (int c = 0; c < 64; c += 4) {
            a0 += hh[c + 0] * wq[(c + 0) * 128 + d];
            a1 += hh[c + 1] * wq[(c + 1) * 128 + d];
            a2 += hh[c + 2] * wq[(c + 2) * 128 + d];
            a3 += hh[c + 3] * wq[(c + 3) * 128 + d];
        }
        hid[tid] = (a0 + a1) + (a2 + a3);
    }
    __syncthreads();
    if (tid < 128)
        g_qb[b * 2048 + s * 128 + tid] =
            __float2bfloat16((hid[tid] + hid[tid + 128]) * QSCALE);
}

// ============================================================================
// Kernel 5: final update + heads.  grid 160, 256 thr.
// ============================================================================
__global__ void k_last(const float* __restrict__ nmw, const float* __restrict__ nmb,
                       const float* __restrict__ w1, const float* __restrict__ b1,
                       const float* __restrict__ w2, const float* __restrict__ b2,
                       const float* __restrict__ pw1, const float* __restrict__ pb1,
                       const float* __restrict__ pw2, const float* __restrict__ pb2,
                       const float* __restrict__ tw, const float* __restrict__ tb,
                       float* __restrict__ out)
{
    __shared__ float sl[128];
    __shared__ float hm[128];
    __shared__ float hid[256];
    __shared__ float r1[8], r2[8];
    __shared__ float sden;
    const int tid = threadIdx.x;
    const int b = blockIdx.x / 10;
    const int s = blockIdx.x % 10;

    if ((tid >> 5) == 4) {
        int lane = tid & 31;
        float p = g_pden[(b * NCHUNK + lane) * S_ + s];
        p = warpRed1(p);
        if (lane == 0) sden = p;
    }
    float u0 = 0, u1 = 0, u2 = 0, u3 = 0;
    if (tid < 128) {
        const float* src = g_pnum + ((size_t)(b * NCHUNK) * S_ + s) * D_ + tid;
        #pragma unroll
        for (int ch = 0; ch < NCHUNK; ch += 4) {
            u0 += __ldcs(src + (size_t)(ch + 0) * S_ * D_);
            u1 += __ldcs(src + (size_t)(ch + 1) * S_ * D_);
            u2 += __ldcs(src + (size_t)(ch + 2) * S_ * D_);
            u3 += __ldcs(src + (size_t)(ch + 3) * S_ * D_);
        }
    }
    __syncthreads();
    float slot_new = 0.f;
    if (tid < 128)
        slot_new = g_slots[(b * S_ + s) * D_ + tid]
                 + ((u0 + u1) + (u2 + u3)) / (sden + 1e-8f);
    float mu, rs;
    ln_stats(tid < 128 ? slot_new : 0.f, r1, r2, mu, rs);
    if (tid < 128) hm[tid] = (slot_new - mu) * rs * nmw[tid] + nmb[tid];
    __syncthreads();
    {
        float a0 = 0, a1 = 0, a2 = 0, a3 = 0;
        #pragma unroll
        for (int c = 0; c < 128; c += 4) {
            a0 += hm[c + 0] * w1[(c + 0) * 256 + tid];
            a1 += hm[c + 1] * w1[(c + 1) * 256 + tid];
            a2 += hm[c + 2] * w1[(c + 2) * 256 + tid];
            a3 += hm[c + 3] * w1[(c + 3) * 256 + tid];
        }
        hid[tid] = fmaxf(b1[tid] + (a0 + a1) + (a2 + a3), 0.f);
    }
    __syncthreads();
    if (tid < 128) {
        float o0 = 0, o1 = 0, o2 = 0, o3 = 0;
        #pragma unroll 16
        for (int j = 0; j < 256; j += 4) {
            o0 += hid[j + 0] * w2[(j + 0) * 128 + tid];
            o1 += hid[j + 1] * w2[(j + 1) * 128 + tid];
            o2 += hid[j + 2] * w2[(j + 2) * 128 + tid];
            o3 += hid[j + 3] * w2[(j + 3) * 128 + tid];
        }
        sl[tid] = slot_new + b2[tid] + (o0 + o1) + (o2 + o3);
    }
    __syncthreads();

    // heads
    {
        float a0 = 0, a1 = 0, a2 = 0, a3 = 0;
        #pragma unroll
        for (int c = 0; c < 128; c += 4) {
            a0 += sl[c + 0] * pw1[(c + 0) * 256 + tid];
            a1 += sl[c + 1] * pw1[(c + 1) * 256 + tid];
            a2 += sl[c + 2] * pw1[(c + 2) * 256 + tid];
            a3 += sl[c + 3] * pw1[(c + 3) * 256 + tid];
        }
        hid[tid] = fmaxf(pb1[tid] + (a0 + a1) + (a2 + a3), 0.f);
    }
    __syncthreads();
    if (tid < 128) {
        float o0 = 0, o1 = 0, o2 = 0, o3 = 0;
        #pragma unroll 16
        for (int j = 0; j < 256; j += 4) {
            o0 += hid[j + 0] * pw2[(j + 0) * 128 + tid];
            o1 += hid[j + 1] * pw2[(j + 1) * 128 + tid];
            o2 += hid[j + 2] * pw2[(j + 2) * 128 + tid];
            o3 += hid[j + 3] * pw2[(j + 3) * 128 + tid];
        }
        out[blockIdx.x * 128 + tid] = pb2[tid] + (o0 + o1) + (o2 + o3);
    } else if (tid < 128 + T_) {
        int tt = tid - 128;
        float o = tb[tt];
        #pragma unroll 4
        for (int c = 0; c < 128; c++) o += sl[c] * tw[c * T_ + tt];
        out[B_ * S_ * D_ + blockIdx.x * T_ + tt] = o;
    }
}

// ============================================================================
extern "C" void kernel_launch(void* const* d_in, const int* in_sizes, int n_in,
                              void* d_out, int out_size)
{
    const float* obs  = (const float*)d_in[0];
    const float* noise= (const float*)d_in[1];
    const float* smu  = (const float*)d_in[2];
    const float* sls  = (const float*)d_in[3];
    const float* niw  = (const float*)d_in[4];
    const float* nib  = (const float*)d_in[5];
    const float* nsw  = (const float*)d_in[6];
    const float* nsb  = (const float*)d_in[7];
    const float* nmw  = (const float*)d_in[8];
    const float* nmb  = (const float*)d_in[9];
    const float* Wq   = (const float*)d_in[10];
    const float* Wk   = (const float*)d_in[11];
    const float* Wv   = (const float*)d_in[12];
    const float* mw1  = (const float*)d_in[13];
    const float* mb1  = (const float*)d_in[14];
    const float* mw2  = (const float*)d_in[15];
    const float* mb2  = (const float*)d_in[16];
    const float* pw1  = (const float*)d_in[17];
    const float* pb1  = (const float*)d_in[18];
    const float* pw2  = (const float*)d_in[19];
    const float* pb2  = (const float*)d_in[20];
    const float* tcw  = (const float*)d_in[21];
    const float* tcb  = (const float*)d_in[22];
    float* out = (float*)d_out;

    cudaFuncSetAttribute(k_ln_kv, cudaFuncAttributeMaxDynamicSharedMemorySize, SMEM1);
    cudaFuncSetAttribute(k_attn,  cudaFuncAttributeMaxDynamicSharedMemorySize, ATT_SMEM);

    // launch order: ncu capture (4th launch) lands on k_attn
    k_prep<<<D_, C_>>>(Wk, Wv);                                          // 1
    k_ln_kv<<<NTOK / 512, 512, SMEM1>>>(obs, niw, nib);                  // 2
    k_sq_init<<<160, 256>>>(noise, smu, sls, nsw, nsb, Wq);              // 3
    dim3 g2(NCHUNK, B_);
    for (int it = 0; it < 3; it++) {
        k_attn<<<g2, 256, ATT_SMEM>>>();                                 // 4 <- ncu
        if (it < 2)
            k_slotq<<<160, 256>>>(nmw, nmb, mw1, mb1, mw2, mb2, nsw, nsb, Wq);
        else
            k_last<<<160, 256>>>(nmw, nmb, mw1, mb1, mw2, mb2,
                                 pw1, pb1, pw2, pb2, tcw, tcb, out);
    }
}

// round 12
// speedup vs baseline: 1.0437x; 1.0437x over previous
#include <cuda_runtime.h>
#include <cuda_bf16.h>
#include <cstdint>

#define B_    16
#define S_    10
#define D_    128
#define C_    256
#define NTOK  65536
#define NPB   4096
#define T_    20
#define CHUNK 128
#define NCHUNK 32
#define QSCALE 0.08838834764831845f

// ---- scratch ----
__device__ __nv_bfloat16 g_k[NTOK * D_];          // [tok][d]
__device__ __nv_bfloat16 g_v[NTOK * D_];          // [tok][d]
__device__ __nv_bfloat16 g_wkT[D_ * C_];          // Wk^T [d][c]
__device__ __nv_bfloat16 g_wvT[D_ * C_];          // Wv^T [d][c]
__device__ __nv_bfloat16 g_qb[B_ * 16 * D_];      // [b][16 slots(pad)][d]
__device__ float g_slots[B_ * S_ * D_];
__device__ float g_pnum[(size_t)B_ * NCHUNK * S_ * D_];
__device__ float g_pden[B_ * NCHUNK * S_];

__device__ __forceinline__ float2 warpRed2(float a, float b) {
    #pragma unroll
    for (int o = 16; o > 0; o >>= 1) {
        a += __shfl_xor_sync(0xffffffffu, a, o);
        b += __shfl_xor_sync(0xffffffffu, b, o);
    }
    return make_float2(a, b);
}
__device__ __forceinline__ float warpRed1(float a) {
    #pragma unroll
    for (int o = 16; o > 0; o >>= 1) a += __shfl_xor_sync(0xffffffffu, a, o);
    return a;
}

__device__ __forceinline__ uint32_t s2u(const void* p) {
    return (uint32_t)__cvta_generic_to_shared(p);
}
__device__ __forceinline__ float bf(const __nv_bfloat16 x) { return __bfloat162float(x); }

#define LDSM4(r, addr)                                                          \
    asm volatile("ldmatrix.sync.aligned.m8n8.x4.shared.b16 {%0,%1,%2,%3}, [%4];"\
                 : "=r"((r)[0]), "=r"((r)[1]), "=r"((r)[2]), "=r"((r)[3])       \
                 : "r"(addr))

#define LDSM4T(r, addr)                                                         \
    asm volatile("ldmatrix.sync.aligned.m8n8.x4.trans.shared.b16 {%0,%1,%2,%3}, [%4];"\
                 : "=r"((r)[0]), "=r"((r)[1]), "=r"((r)[2]), "=r"((r)[3])       \
                 : "r"(addr))

#define MMA_BF16(d, a, b0, b1)                                                  \
    asm volatile("mma.sync.aligned.m16n8k16.row.col.f32.bf16.bf16.f32 "         \
                 "{%0,%1,%2,%3}, {%4,%5,%6,%7}, {%8,%9}, {%0,%1,%2,%3};"        \
                 : "+f"((d)[0]), "+f"((d)[1]), "+f"((d)[2]), "+f"((d)[3])       \
                 : "r"((a)[0]), "r"((a)[1]), "r"((a)[2]), "r"((a)[3]),          \
                   "r"(b0), "r"(b1))

// cp.async 16B (L2-only .cg path) + group control
#define CPASYNC16(dst, src)                                                     \
    asm volatile("cp.async.cg.shared.global [%0], [%1], 16;"                    \
                 :: "r"(dst), "l"(src) : "memory")
#define CPCOMMIT() asm volatile("cp.async.commit_group;" ::: "memory")
#define CPWAIT(n)  asm volatile("cp.async.wait_group %0;" :: "n"(n) : "memory")

// ============================================================================
// Kernel 0a/0b: weight transpose + bf16 convert (split for ncu slot align)
// ============================================================================
__global__ void k_prepk(const float* __restrict__ Wk)
{
    int d = blockIdx.x, c = threadIdx.x;
    g_wkT[d * C_ + c] = __float2bfloat16(Wk[c * D_ + d]);
}
__global__ void k_prepv(const float* __restrict__ Wv)
{
    int d = blockIdx.x, c = threadIdx.x;
    g_wvT[d * C_ + c] = __float2bfloat16(Wv[c * D_ + d]);
}

// ============================================================================
// Kernel 1: fused LayerNorm + K,V projection, WARP-SPECIALIZED.
// 512 tokens/block, 512 threads, 128 blocks (single wave).
// Warps 8-15 (producers): LayerNorm 64-token half-tiles into double-buffered A.
// Warps 0-7 (consumers): 4 K-warps + 4 V-warps, each m32 x n64 MMA + epilogue.
// LN of half h+1 overlaps MMA of half h.
// ============================================================================
#define XSTRIDE 264
#define SMEM1 (3 * 128 * XSTRIDE * 2)
__global__ __launch_bounds__(512, 1) void k_ln_kv(
    const float* __restrict__ obs, const float* __restrict__ niw,
    const float* __restrict__ nib)
{
    extern __shared__ char smx[];
    __nv_bfloat16* ha0 = (__nv_bfloat16*)smx;           // [64][264]
    __nv_bfloat16* ha1 = ha0 + 64 * XSTRIDE;            // [64][264]
    __nv_bfloat16* wks = ha1 + 64 * XSTRIDE;            // [128][264]
    __nv_bfloat16* wvs = wks + 128 * XSTRIDE;

    const int tid  = threadIdx.x;
    const int wid  = tid >> 5;
    const int lane = tid & 31;
    const int tblk = blockIdx.x * 512;

    // stage bf16 transposed weights once per block (all 512 threads)
    {
        const uint4* gk4 = (const uint4*)g_wkT;
        const uint4* gv4 = (const uint4*)g_wvT;
        #pragma unroll
        for (int i = 0; i < 8; i++) {
            int u = tid + i * 512;
            int row = u >> 5, c = u & 31;
            *(uint4*)((char*)wks + row * (XSTRIDE * 2) + c * 16) = gk4[u];
            *(uint4*)((char*)wvs + row * (XSTRIDE * 2) + c * 16) = gv4[u];
        }
    }

    if (wid >= 8) {
        // ================= PRODUCER: LayerNorm =================
        const int p  = wid - 8;                 // 0..7, rows p*8..p*8+7 of the half
        const int c0 = lane * 4;
        float4 nw0 = *(const float4*)(niw + c0);
        float4 nw1 = *(const float4*)(niw + c0 + 128);
        float4 nb0 = *(const float4*)(nib + c0);
        float4 nb1 = *(const float4*)(nib + c0 + 128);

        // prologue: half 0 -> ha0; then halves 1..7 inside the loop
        #pragma unroll 1
        for (int h = -1; h < 8; h++) {
            if (h < 7) {
                const int hh = h + 1;
                __nv_bfloat16* buf = (hh & 1) ? ha1 : ha0;
                const int t0 = tblk + hh * 64;
                #pragma unroll
                for (int i = 0; i < 8; i++) {
                    int r = p * 8 + i;
                    const float4* src = (const float4*)(obs + (size_t)(t0 + r) * C_);
                    float4 v0 = __ldcs(src + lane);
                    float4 v1 = __ldcs(src + lane + 32);
                    float s  = v0.x + v0.y + v0.z + v0.w + v1.x + v1.y + v1.z + v1.w;
                    float ss = v0.x*v0.x + v0.y*v0.y + v0.z*v0.z + v0.w*v0.w
                             + v1.x*v1.x + v1.y*v1.y + v1.z*v1.z + v1.w*v1.w;
                    float2 red = warpRed2(s, ss);
                    float mu  = red.x * (1.0f / 256.0f);
                    float var = red.y * (1.0f / 256.0f) - mu * mu;
                    float rsg = rsqrtf(var + 1e-5f);
                    char* xr = (char*)buf + r * (XSTRIDE * 2);
                    *(__nv_bfloat162*)(xr + (c0 + 0) * 2) =
                        __floats2bfloat162_rn((v0.x - mu) * rsg * nw0.x + nb0.x,
                                              (v0.y - mu) * rsg * nw0.y + nb0.y);
                    *(__nv_bfloat162*)(xr + (c0 + 2) * 2) =
                        __floats2bfloat162_rn((v0.z - mu) * rsg * nw0.z + nb0.z,
                                              (v0.w - mu) * rsg * nw0.w + nb0.w);
                    *(__nv_bfloat162*)(xr + (c0 + 128) * 2) =
                        __floats2bfloat162_rn((v1.x - mu) * rsg * nw1.x + nb1.x,
                                              (v1.y - mu) * rsg * nw1.y + nb1.y);
                    *(__nv_bfloat162*)(xr + (c0 + 130) * 2) =
                        __floats2bfloat162_rn((v1.z - mu) * rsg * nw1.z + nb1.z,
                                              (v1.w - mu) * rsg * nw1.w + nb1.w);
                }
            }
            __syncthreads();
        }
    } else {
        // ================= CONSUMER: MMA + epilogue =================
        const int mat = wid >> 2;          // 0 = K (warps 0-3), 1 = V (warps 4-7)
        const int wm  = wid & 1;           // m half (32 rows of 64)
        const int wn  = (wid >> 1) & 1;    // n half (64 cols of 128)
        const __nv_bfloat16* wsm = mat ? wvs : wks;
        const int ga = lane >> 3, ra = lane & 7;
        const uint32_t aB0 = s2u(wsm) +
            (uint32_t)(((wn * 64 + ra + ((ga >> 1) << 3)) * XSTRIDE + ((ga & 1) << 3)) * 2);
        const uint32_t aAoff =
            (uint32_t)(((wm * 32 + ra + ((ga & 1) << 3)) * XSTRIDE + ((ga >> 1) << 3)) * 2);
        const int qrow = lane >> 2;
        const int qcol = (lane & 3) * 2;
        __nv_bfloat16* gout = mat ? g_v : g_k;

        __syncthreads();    // matches producers' prologue barrier
        #pragma unroll 1
        for (int h = 0; h < 8; h++) {
            const __nv_bfloat16* abuf = (h & 1) ? ha1 : ha0;
            uint32_t aA = s2u(abuf) + aAoff;
            uint32_t aB = aB0;

            float acc[2][8][4];
            #pragma unroll
            for (int mi = 0; mi < 2; mi++)
                #pragma unroll
                for (int nj = 0; nj < 8; nj++)
                    #pragma unroll
                    for (int e = 0; e < 4; e++) acc[mi][nj][e] = 0.f;

            #pragma unroll 1
            for (int s = 0; s < 16; s++) {
                uint32_t A0[4], A1[4], Bx[4][4];
                LDSM4(A0, aA);
                LDSM4(A1, aA + 16 * (XSTRIDE * 2));
                #pragma unroll
                for (int j = 0; j < 4; j++)
                    LDSM4(Bx[j], aB + j * 16 * (XSTRIDE * 2));
                #pragma unroll
                for (int nj = 0; nj < 8; nj++) {
                    uint32_t b0 = Bx[nj >> 1][(nj & 1) * 2];
                    uint32_t b1 = Bx[nj >> 1][(nj & 1) * 2 + 1];
                    MMA_BF16(acc[0][nj], A0, b0, b1);
                    MMA_BF16(acc[1][nj], A1, b0, b1);
                }
                aA += 32;
                aB += 32;
            }

            const int rbase = tblk + h * 64 + wm * 32;
            #pragma unroll
            for (int mi = 0; mi < 2; mi++) {
                #pragma unroll
                for (int nj = 0; nj < 8; nj++) {
                    int c  = wn * 64 + nj * 8 + qcol;
                    int r0 = rbase + mi * 16 + qrow;
                    *(__nv_bfloat162*)(gout + (size_t)r0 * D_ + c) =
                        __floats2bfloat162_rn(acc[mi][nj][0], acc[mi][nj][1]);
                    *(__nv_bfloat162*)(gout + (size_t)(r0 + 8) * D_ + c) =
                        __floats2bfloat162_rn(acc[mi][nj][2], acc[mi][nj][3]);
                }
            }
            __syncthreads();
        }
    }
}

// ============================================================================
// LN stats helper (256-thread block, 128 live values)
// ============================================================================
__device__ __forceinline__ void ln_stats(float x, float* r1, float* r2,
                                         float& mu, float& rs) {
    float2 red = warpRed2(x, x * x);
    int wid = threadIdx.x >> 5, lane = threadIdx.x & 31;
    if (lane == 0) { r1[wid] = red.x; r2[wid] = red.y; }
    __syncthreads();
    float Sm = 0.f, Sq = 0.f;
    #pragma unroll
    for (int i = 0; i < 8; i++) { Sm += r1[i]; Sq += r2[i]; }
    mu = Sm * (1.0f / 128.0f);
    float var = Sq * (1.0f / 128.0f) - mu * mu;
    rs = rsqrtf(var + 1e-5f);
}

// ============================================================================
// Kernel 2: slot init + q-pad zero + LN + q projection (fused).
// ============================================================================
__global__ void k_sq_init(const float* __restrict__ noise, const float* __restrict__ smu,
                          const float* __restrict__ sls, const float* __restrict__ nsw,
                          const float* __restrict__ nsb, const float* __restrict__ Wq)
{
    __shared__ float sl[128];
    __shared__ float hm[128];
    __shared__ float hid[256];
    __shared__ float r1[8], r2[8];
    const int tid = threadIdx.x;
    const int b = blockIdx.x / 10;
    const int s = blockIdx.x % 10;

    if (tid < 128) {
        float v = smu[tid] + expf(sls[tid]) * noise[blockIdx.x * 128 + tid];
        g_slots[blockIdx.x * 128 + tid] = v;
        sl[tid] = v;
        if (s < 6)
            g_qb[b * 2048 + (10 + s) * 128 + tid] = __float2bfloat16(0.f);
    }
    __syncthreads();

    float x = (tid < 128) ? sl[tid] : 0.f;
    float mu, rs;
    ln_stats(x, r1, r2, mu, rs);
    if (tid < 128) hm[tid] = (x - mu) * rs * nsw[tid] + nsb[tid];
    __syncthreads();
    {
        int d = tid & 127, half = tid >> 7;
        const float* wq = Wq + half * 64 * 128;
        const float* hh = hm + half * 64;
        float a0 = 0, a1 = 0, a2 = 0, a3 = 0;
        #pragma unroll
        for (int c = 0; c < 64; c += 4) {
            a0 += hh[c + 0] * wq[(c + 0) * 128 + d];
            a1 += hh[c + 1] * wq[(c + 1) * 128 + d];
            a2 += hh[c + 2] * wq[(c + 2) * 128 + d];
            a3 += hh[c + 3] * wq[(c + 3) * 128 + d];
        }
        hid[tid] = (a0 + a1) + (a2 + a3);
    }
    __syncthreads();
    if (tid < 128)
        g_qb[b * 2048 + s * 128 + tid] =
            __float2bfloat16((hid[tid] + hid[tid + 128]) * QSCALE);
}

// ============================================================================
// Kernel 3: fused attention chunk, cp.async K/V prefetch.
// grid (NCHUNK, B_), 256 threads, 2 CTAs/SM (87KB smem).
// ============================================================================
#define TS 136
#define LSTR 132
#define ATT_SMEM (2*128*TS*2 + 16*TS*2 + 16*TS*2 + 16*LSTR*4)
__global__ __launch_bounds__(256, 2) void k_attn()
{
    extern __shared__ char sm2[];
    __nv_bfloat16* tileK = (__nv_bfloat16*)sm2;             // [128][136]
    __nv_bfloat16* tileV = tileK + 128 * TS;                // [128][136]
    __nv_bfloat16* Qs    = tileV + 128 * TS;                // [16][136]
    __nv_bfloat16* aBm   = Qs + 16 * TS;                    // attn bf16 [16][136]
    float* Ls            = (float*)(aBm + 16 * TS);         // logits [16][132]

    const int tid  = threadIdx.x;
    const int w    = tid >> 5;
    const int lane = tid & 31;
    const int ck   = blockIdx.x;
    const int b    = blockIdx.y;

    // ---- issue async loads: K (group A) then V (group B) ----
    {
        const uint4* srcK = (const uint4*)(g_k + ((size_t)b * NPB + ck * CHUNK) * D_);
        const uint4* srcV = (const uint4*)(g_v + ((size_t)b * NPB + ck * CHUNK) * D_);
        const uint32_t dK = s2u(tileK), dV = s2u(tileV);
        #pragma unroll
        for (int i = 0; i < 8; i++) {
            int u = tid + i * 256;
            int row = u >> 4, c = u & 15;
            CPASYNC16(dK + row * (TS * 2) + c * 16, srcK + u);
        }
        CPCOMMIT();
        #pragma unroll
        for (int i = 0; i < 8; i++) {
            int u = tid + i * 256;
            int row = u >> 4, c = u & 15;
            CPASYNC16(dV + row * (TS * 2) + c * 16, srcV + u);
        }
        CPCOMMIT();
    }

    // load Q [16][128] : 256 uint4
    {
        int row = tid >> 4, c = tid & 15;
        *(uint4*)((char*)Qs + row * (TS * 2) + c * 16) =
            ((const uint4*)(g_qb + b * 2048))[tid];
    }
    if (tid < 102) {
        *(uint4*)((char*)aBm + 10 * (TS * 2) + tid * 16) = make_uint4(0, 0, 0, 0);
    }

    CPWAIT(1);          // K tile ready
    __syncthreads();

    const int ga = lane >> 3, ra = lane & 7;
    const int qrow = lane >> 2, qcol = (lane & 3) * 2;
    const uint32_t baseA_q = s2u(Qs) +
        (uint32_t)(((ra + ((ga & 1) << 3)) * TS + ((ga >> 1) << 3)) * 2);
    const uint32_t baseB_k = s2u(tileK) +
        (uint32_t)(((w * 16 + ra + ((ga >> 1) << 3)) * TS + ((ga & 1) << 3)) * 2);

    // ---- logits MMA: l[s][t] ----
    {
        float lacc[2][4] = {{0,0,0,0},{0,0,0,0}};
        #pragma unroll
        for (int ks = 0; ks < 8; ks++) {
            uint32_t A[4], Bx[4];
            LDSM4(A, baseA_q + ks * 32);
            LDSM4(Bx, baseB_k + ks * 32);
            MMA_BF16(lacc[0], A, Bx[0], Bx[1]);
            MMA_BF16(lacc[1], A, Bx[2], Bx[3]);
        }
        #pragma unroll
        for (int nj = 0; nj < 2; nj++) {
            int t = w * 16 + nj * 8 + qcol;
            Ls[qrow * LSTR + t]           = lacc[nj][0];
            Ls[qrow * LSTR + t + 1]       = lacc[nj][1];
            Ls[(qrow + 8) * LSTR + t]     = lacc[nj][2];
            Ls[(qrow + 8) * LSTR + t + 1] = lacc[nj][3];
        }
    }
    __syncthreads();

    // ---- softmax over 10 slots per token ----
    if (tid < 128) {
        float v[10]; float m = -1e30f;
        #pragma unroll
        for (int s = 0; s < 10; s++) { v[s] = Ls[s * LSTR + tid]; m = fmaxf(m, v[s]); }
        float sum = 0.f;
        #pragma unroll
        for (int s = 0; s < 10; s++) { v[s] = __expf(v[s] - m); sum += v[s]; }
        float inv = 1.0f / sum;
        #pragma unroll
        for (int s = 0; s < 10; s++) aBm[s * TS + tid] = __float2bfloat16(v[s] * inv);
    }
    __syncthreads();

    // ---- denominators ----
    for (int s = w; s < 10; s += 8) {
        float p = bf(aBm[s * TS + lane]) + bf(aBm[s * TS + lane + 32])
                + bf(aBm[s * TS + lane + 64]) + bf(aBm[s * TS + lane + 96]);
        p = warpRed1(p);
        if (lane == 0) g_pden[(b * NCHUNK + ck) * S_ + s] = p;
    }

    CPWAIT(0);          // V tile ready
    __syncthreads();

    // ---- numerator MMA: upd[s][d] = sum_t attn[s][t] * V[t][d] (trans B) ----
    {
        const uint32_t baseA_a = s2u(aBm) +
            (uint32_t)(((ra + ((ga & 1) << 3)) * TS + ((ga >> 1) << 3)) * 2);
        const uint32_t baseB_v = s2u(tileV) +
            (uint32_t)(((((ga & 1) << 3) + ra) * TS + w * 16 + ((ga >> 1) << 3)) * 2);
        float nacc[2][4] = {{0,0,0,0},{0,0,0,0}};
        #pragma unroll
        for (int ks = 0; ks < 8; ks++) {
            uint32_t A[4], Bt[4];
            LDSM4(A, baseA_a + ks * 32);
            LDSM4T(Bt, baseB_v + ks * (16 * TS * 2));
            MMA_BF16(nacc[0], A, Bt[0], Bt[1]);
            MMA_BF16(nacc[1], A, Bt[2], Bt[3]);
        }
        float* dst = g_pnum + (size_t)(b * NCHUNK + ck) * S_ * D_;
        #pragma unroll
        for (int nj = 0; nj < 2; nj++) {
            int d = w * 16 + nj * 8 + qcol;
            *(float2*)(dst + qrow * D_ + d) = make_float2(nacc[nj][0], nacc[nj][1]);
            if (qrow + 8 < 10)
                *(float2*)(dst + (qrow + 8) * D_ + d) = make_float2(nacc[nj][2], nacc[nj][3]);
        }
    }
}

// ============================================================================
// Kernel 4: slot update + q projection.  grid 160, 256 thr.
// ============================================================================
__global__ void k_slotq(const float* __restrict__ nmw, const float* __restrict__ nmb,
                        const float* __restrict__ w1, const float* __restrict__ b1,
                        const float* __restrict__ w2, const float* __restrict__ b2,
                        const float* __restrict__ nsw, const float* __restrict__ nsb,
                        const float* __restrict__ Wq)
{
    __shared__ float sl[128];
    __shared__ float hm[128];
    __shared__ float hid[256];
    __shared__ float r1[8], r2[8];
    __shared__ float sden;
    const int tid = threadIdx.x;
    const int b = blockIdx.x / 10;
    const int s = blockIdx.x % 10;

    if ((tid >> 5) == 4) {
        int lane = tid & 31;
        float p = g_pden[(b * NCHUNK + lane) * S_ + s];
        p = warpRed1(p);
        if (lane == 0) sden = p;
    }
    float u0 = 0, u1 = 0, u2 = 0, u3 = 0;
    if (tid < 128) {
        const float* src = g_pnum + ((size_t)(b * NCHUNK) * S_ + s) * D_ + tid;
        #pragma unroll
        for (int ch = 0; ch < NCHUNK; ch += 4) {
            u0 += __ldcs(src + (size_t)(ch + 0) * S_ * D_);
            u1 += __ldcs(src + (size_t)(ch + 1) * S_ * D_);
            u2 += __ldcs(src + (size_t)(ch + 2) * S_ * D_);
            u3 += __ldcs(src + (size_t)(ch + 3) * S_ * D_);
        }
    }
    __syncthreads();
    float slot_new = 0.f;
    if (tid < 128)
        slot_new = g_slots[(b * S_ + s) * D_ + tid]
                 + ((u0 + u1) + (u2 + u3)) / (sden + 1e-8f);
    float mu, rs;
    ln_stats(tid < 128 ? slot_new : 0.f, r1, r2, mu, rs);
    if (tid < 128) hm[tid] = (slot_new - mu) * rs * nmw[tid] + nmb[tid];
    __syncthreads();
    {
        float a0 = 0, a1 = 0, a2 = 0, a3 = 0;
        #pragma unroll
        for (int c = 0; c < 128; c += 4) {
            a0 += hm[c + 0] * w1[(c + 0) * 256 + tid];
            a1 += hm[c + 1] * w1[(c + 1) * 256 + tid];
            a2 += hm[c + 2] * w1[(c + 2) * 256 + tid];
            a3 += hm[c + 3] * w1[(c + 3) * 256 + tid];
        }
        hid[tid] = fmaxf(b1[tid] + (a0 + a1) + (a2 + a3), 0.f);
    }
    __syncthreads();
    if (tid < 128) {
        float o0 = 0, o1 = 0, o2 = 0, o3 = 0;
        #pragma unroll 16
        for (int j = 0; j < 256; j += 4) {
            o0 += hid[j + 0] * w2[(j + 0) * 128 + tid];
            o1 += hid[j + 1] * w2[(j + 1) * 128 + tid];
            o2 += hid[j + 2] * w2[(j + 2) * 128 + tid];
            o3 += hid[j + 3] * w2[(j + 3) * 128 + tid];
        }
        float sf = slot_new + b2[tid] + (o0 + o1) + (o2 + o3);
        sl[tid] = sf;
        g_slots[(b * S_ + s) * D_ + tid] = sf;
    }
    __syncthreads();

    // LN(ns) + q = h @ Wq * scale (split-k over 2 halves)
    float x = (tid < 128) ? sl[tid] : 0.f;
    ln_stats(x, r1, r2, mu, rs);
    if (tid < 128) hm[tid] = (x - mu) * rs * nsw[tid] + nsb[tid];
    __syncthreads();
    {
        int d = tid & 127, half = tid >> 7;
        const float* wq = Wq + half * 64 * 128;
        const float* hh = hm + half * 64;
        float a0 = 0, a1 = 0, a2 = 0, a3 = 0;
        #pragma unroll
        for (int c = 0; c < 64; c += 4) {
            a0 += hh[c + 0] * wq[(c + 0) * 128 + d];
            a1 += hh[c + 1] * wq[(c + 1) * 128 + d];
            a2 += hh[c + 2] * wq[(c + 2) * 128 + d];
            a3 += hh[c + 3] * wq[(c + 3) * 128 + d];
        }
        hid[tid] = (a0 + a1) + (a2 + a3);
    }
    __syncthreads();
    if (tid < 128)
        g_qb[b * 2048 + s * 128 + tid] =
            __float2bfloat16((hid[tid] + hid[tid + 128]) * QSCALE);
}

// ============================================================================
// Kernel 5: final update + heads.  grid 160, 256 thr.
// ============================================================================
__global__ void k_last(const float* __restrict__ nmw, const float* __restrict__ nmb,
                       const float* __restrict__ w1, const float* __restrict__ b1,
                       const float* __restrict__ w2, const float* __restrict__ b2,
                       const float* __restrict__ pw1, const float* __restrict__ pb1,
                       const float* __restrict__ pw2, const float* __restrict__ pb2,
                       const float* __restrict__ tw, const float* __restrict__ tb,
                       float* __restrict__ out)
{
    __shared__ float sl[128];
    __shared__ float hm[128];
    __shared__ float hid[256];
    __shared__ float r1[8], r2[8];
    __shared__ float sden;
    const int tid = threadIdx.x;
    const int b = blockIdx.x / 10;
    const int s = blockIdx.x % 10;

    if ((tid >> 5) == 4) {
        int lane = tid & 31;
        float p = g_pden[(b * NCHUNK + lane) * S_ + s];
        p = warpRed1(p);
        if (lane == 0) sden = p;
    }
    float u0 = 0, u1 = 0, u2 = 0, u3 = 0;
    if (tid < 128) {
        const float* src = g_pnum + ((size_t)(b * NCHUNK) * S_ + s) * D_ + tid;
        #pragma unroll
        for (int ch = 0; ch < NCHUNK; ch += 4) {
            u0 += __ldcs(src + (size_t)(ch + 0) * S_ * D_);
            u1 += __ldcs(src + (size_t)(ch + 1) * S_ * D_);
            u2 += __ldcs(src + (size_t)(ch + 2) * S_ * D_);
            u3 += __ldcs(src + (size_t)(ch + 3) * S_ * D_);
        }
    }
    __syncthreads();
    float slot_new = 0.f;
    if (tid < 128)
        slot_new = g_slots[(b * S_ + s) * D_ + tid]
                 + ((u0 + u1) + (u2 + u3)) / (sden + 1e-8f);
    float mu, rs;
    ln_stats(tid < 128 ? slot_new : 0.f, r1, r2, mu, rs);
    if (tid < 128) hm[tid] = (slot_new - mu) * rs * nmw[tid] + nmb[tid];
    __syncthreads();
    {
        float a0 = 0, a1 = 0, a2 = 0, a3 = 0;
        #pragma unroll
        for (int c = 0; c < 128; c += 4) {
            a0 += hm[c + 0] * w1[(c + 0) * 256 + tid];
            a1 += hm[c + 1] * w1[(c + 1) * 256 + tid];
            a2 += hm[c + 2] * w1[(c + 2) * 256 + tid];
            a3 += hm[c + 3] * w1[(c + 3) * 256 + tid];
        }
        hid[tid] = fmaxf(b1[tid] + (a0 + a1) + (a2 + a3), 0.f);
    }
    __syncthreads();
    if (tid < 128) {
        float o0 = 0, o1 = 0, o2 = 0, o3 = 0;
        #pragma unroll 16
        for (int j = 0; j < 256; j += 4) {
            o0 += hid[j + 0] * w2[(j + 0) * 128 + tid];
            o1 += hid[j + 1] * w2[(j + 1) * 128 + tid];
            o2 += hid[j + 2] * w2[(j + 2) * 128 + tid];
            o3 += hid[j + 3] * w2[(j + 3) * 128 + tid];
        }
        sl[tid] = slot_new + b2[tid] + (o0 + o1) + (o2 + o3);
    }
    __syncthreads();

    // heads
    {
        float a0 = 0, a1 = 0, a2 = 0, a3 = 0;
        #pragma unroll
        for (int c = 0; c < 128; c += 4) {
            a0 += sl[c + 0] * pw1[(c + 0) * 256 + tid];
            a1 += sl[c + 1] * pw1[(c + 1) * 256 + tid];
            a2 += sl[c + 2] * pw1[(c + 2) * 256 + tid];
            a3 += sl[c + 3] * pw1[(c + 3) * 256 + tid];
        }
        hid[tid] = fmaxf(pb1[tid] + (a0 + a1) + (a2 + a3), 0.f);
    }
    __syncthreads();
    if (tid < 128) {
        float o0 = 0, o1 = 0, o2 = 0, o3 = 0;
        #pragma unroll 16
        for (int j = 0; j < 256; j += 4) {
            o0 += hid[j + 0] * pw2[(j + 0) * 128 + tid];
            o1 += hid[j + 1] * pw2[(j + 1) * 128 + tid];
            o2 += hid[j + 2] * pw2[(j + 2) * 128 + tid];
            o3 += hid[j + 3] * pw2[(j + 3) * 128 + tid];
        }
        out[blockIdx.x * 128 + tid] = pb2[tid] + (o0 + o1) + (o2 + o3);
    } else if (tid < 128 + T_) {
        int tt = tid - 128;
        float o = tb[tt];
        #pragma unroll 4
        for (int c = 0; c < 128; c++) o += sl[c] * tw[c * T_ + tt];
        out[B_ * S_ * D_ + blockIdx.x * T_ + tt] = o;
    }
}

// ============================================================================
extern "C" void kernel_launch(void* const* d_in, const int* in_sizes, int n_in,
                              void* d_out, int out_size)
{
    const float* obs  = (const float*)d_in[0];
    const float* noise= (const float*)d_in[1];
    const float* smu  = (const float*)d_in[2];
    const float* sls  = (const float*)d_in[3];
    const float* niw  = (const float*)d_in[4];
    const float* nib  = (const float*)d_in[5];
    const float* nsw  = (const float*)d_in[6];
    const float* nsb  = (const float*)d_in[7];
    const float* nmw  = (const float*)d_in[8];
    const float* nmb  = (const float*)d_in[9];
    const float* Wq   = (const float*)d_in[10];
    const float* Wk   = (const float*)d_in[11];
    const float* Wv   = (const float*)d_in[12];
    const float* mw1  = (const float*)d_in[13];
    const float* mb1  = (const float*)d_in[14];
    const float* mw2  = (const float*)d_in[15];
    const float* mb2  = (const float*)d_in[16];
    const float* pw1  = (const float*)d_in[17];
    const float* pb1  = (const float*)d_in[18];
    const float* pw2  = (const float*)d_in[19];
    const float* pb2  = (const float*)d_in[20];
    const float* tcw  = (const float*)d_in[21];
    const float* tcb  = (const float*)d_in[22];
    float* out = (float*)d_out;

    cudaFuncSetAttribute(k_ln_kv, cudaFuncAttributeMaxDynamicSharedMemorySize, SMEM1);
    cudaFuncSetAttribute(k_attn,  cudaFuncAttributeMaxDynamicSharedMemorySize, ATT_SMEM);

    // launch order: ncu capture (4th launch) lands on k_ln_kv
    k_prepk<<<D_, C_>>>(Wk);                                             // 1
    k_prepv<<<D_, C_>>>(Wv);                                             // 2
    k_sq_init<<<160, 256>>>(noise, smu, sls, nsw, nsb, Wq);              // 3
    k_ln_kv<<<NTOK / 512, 512, SMEM1>>>(obs, niw, nib);                  // 4 <- ncu
    dim3 g2(NCHUNK, B_);
    for (int it = 0; it < 3; it++) {
        k_attn<<<g2, 256, ATT_SMEM>>>();
        if (it < 2)
            k_slotq<<<160, 256>>>(nmw, nmb, mw1, mb1, mw2, mb2, nsw, nsb, Wq);
        else
            k_last<<<160, 256>>>(nmw, nmb, mw1, mb1, mw2, mb2,
                                 pw1, pb1, pw2, pb2, tcw, tcb, out);
    }
}